// round 1
// baseline (speedup 1.0000x reference)
#include <cuda_runtime.h>
#include <cuda_bf16.h>

#define BN 8
#define MO 12
#define DD 512
#define NO 37
#define NA 6
#define NT 3
#define EM 128
#define NAA 100
#define NC 300
#define KK 72
#define PP 5112            // KK*(KK-1)
#define FD 1536
#define HF 768

// output layout (flattened, tuple order)
#define OFF_FINAL 0                         // B*NC          = 2400
#define OFF_PL    (BN*NC)                   // B*P*3         = 122688
#define OFF_TT    (OFF_PL + BN*PP*NT)       // B*P*3
#define OFF_ACT   (OFF_TT + BN*PP*NT)       // B*MO*NA       = 576
#define OFF_OBJ   (OFF_ACT + BN*MO*NA)      // B*MO*NO       = 3552

// ---------------- device scratch (no allocations allowed) ----------------
__device__ float    g_s1[BN*KK*NT];
__device__ float    g_s2[BN*KK*NT];
__device__ int      g_pos[BN*PP];
__device__ int      g_sel[BN*KK];
__device__ int      g_aaidx[BN*KK];
__device__ int      g_objidx[BN*MO];
__device__ float    g_nonexist[BN*NC];
__device__ unsigned g_segmax[BN*NC];
__device__ int      g_count[BN*NC];
__device__ float    g_invconst[NT];

__device__ __forceinline__ float warpsum(float v){
    #pragma unroll
    for(int o=16;o>0;o>>=1) v += __shfl_xor_sync(0xffffffffu, v, o);
    return v;
}
// monotonic float <-> unsigned mapping for atomicMax on floats of any sign
__device__ __forceinline__ unsigned fmap(float f){
    unsigned u=__float_as_uint(f);
    return (u & 0x80000000u) ? ~u : (u | 0x80000000u);
}
__device__ __forceinline__ float funmap(unsigned u){
    return __uint_as_float((u & 0x80000000u) ? (u ^ 0x80000000u) : ~u);
}

// ---------------- k0: reset per-launch accumulators ----------------
__global__ void k0_init(){
    int i = blockIdx.x*blockDim.x + threadIdx.x;
    if(i < BN*NC){ g_segmax[i] = 0u; g_count[i] = 0; }
}

// ---------------- k1: per (b,obj) classifier heads + selection ----------------
__global__ void k1_heads(const float* __restrict__ inp, const float* __restrict__ objmask,
                         const float* __restrict__ W_obj, const float* __restrict__ b_obj,
                         const float* __restrict__ W_act, const float* __restrict__ b_act,
                         const int*   __restrict__ AA,    float* __restrict__ out){
    int bo = blockIdx.x;           // b*MO + o
    int b  = bo / MO, o = bo % MO;
    __shared__ float row[DD];
    __shared__ float res[NO+NA];
    const float* ir = inp + (size_t)bo*DD;
    for(int d=threadIdx.x; d<DD; d+=blockDim.x) row[d]=ir[d];
    __syncthreads();
    int w = threadIdx.x>>5, lane = threadIdx.x&31;
    for(int c=w; c<NO+NA; c+=8){
        const float* W = (c<NO) ? (W_obj + c*DD) : (W_act + (c-NO)*DD);
        float acc=0.f;
        for(int d=lane; d<DD; d+=32) acc += row[d]*W[d];
        acc = warpsum(acc);
        if(lane==0){
            float v = acc + (c<NO ? b_obj[c] : b_act[c-NO]);
            res[c]=v;
            if(c<NO) out[OFF_OBJ + bo*NO + c]      = v;
            else     out[OFF_ACT + bo*NA + (c-NO)] = v;
        }
    }
    __syncthreads();
    if(threadIdx.x==0){
        int best=0; float bv=res[0];
        for(int c=1;c<NO;c++) if(res[c]>bv){ bv=res[c]; best=c; }
        g_objidx[bo]=best;
    }
    if(threadIdx.x < NA){
        int a = threadIdx.x;
        int k = o*NA + a;
        // sigmoid(x)>0.5 <=> x>0 ; pred_act*mask == 1.0 requires mask == 1.0
        bool act_on = (res[NO+a] > 0.0f) && (objmask[bo] == 1.0f);
        int  aa = AA[b*KK + k];
        bool s  = act_on && (aa != -1);
        g_sel[b*KK+k]   = s ? 1 : 0;
        g_aaidx[b*KK+k] = s ? aa : -1;
    }
}

// ---------------- k2: pooled mean -> non_exist_out ; invalid-pair constant ----------------
__global__ void k2_pool(const float* __restrict__ inp, const float* __restrict__ objmask,
                        const float* __restrict__ W_ne, const float* __restrict__ b_ne,
                        const float* __restrict__ W_tr, const float* __restrict__ b_tr){
    int b = blockIdx.x;
    __shared__ float pooled[DD];
    __shared__ float msum_s;
    if(threadIdx.x==0){
        float m=0.f;
        for(int o=0;o<MO;o++) m += objmask[b*MO+o];
        msum_s=m;
    }
    __syncthreads();
    float msum = msum_s;
    for(int d=threadIdx.x; d<DD; d+=blockDim.x){
        float s=0.f;
        for(int o=0;o<MO;o++) s += inp[((size_t)b*MO+o)*DD + d]*objmask[b*MO+o];
        pooled[d] = s/msum;
    }
    __syncthreads();
    int w=threadIdx.x>>5, lane=threadIdx.x&31;
    for(int c=w; c<NC; c+=8){
        float acc=0.f;
        for(int d=lane; d<DD; d+=32) acc += pooled[d]*W_ne[c*DD+d];
        acc = warpsum(acc);
        if(lane==0) g_nonexist[b*NC+c] = acc + b_ne[c];
    }
    if(b==0 && w<NT){
        float acc=0.f;
        for(int d=lane; d<FD; d+=32) acc += W_tr[w*FD+d];
        acc = warpsum(acc);
        if(lane==0) g_invconst[w] = b_tr[w] - acc;
    }
}

// ---------------- k3: per-slot half-dot factors s1/s2 (one warp per slot) ----------------
__global__ void k3_slots(const float* __restrict__ inp, const float* __restrict__ obj_emb,
                         const float* __restrict__ act_emb, const float* __restrict__ W_tr){
    int warp = (blockIdx.x*blockDim.x + threadIdx.x) >> 5;
    int lane = threadIdx.x & 31;
    if(warp >= BN*KK) return;
    int b = warp/KK, k = warp%KK;
    int o = k/NA,    a = k%NA;
    int oi = g_objidx[b*MO + o];
    const float* ir = inp     + ((size_t)b*MO + o)*DD;
    const float* oe = obj_emb + (size_t)oi*EM;
    const float* ae = act_emb + (size_t)a*EM;
    float acc[NT][2];
    #pragma unroll
    for(int t=0;t<NT;t++){ acc[t][0]=0.f; acc[t][1]=0.f; }
    for(int d=lane; d<HF; d+=32){
        float src = (d<DD) ? ir[d] : (d<DD+EM ? oe[d-DD] : ae[d-DD-EM]);
        #pragma unroll
        for(int t=0;t<NT;t++){
            acc[t][0] += src * W_tr[t*FD + d];
            acc[t][1] += src * W_tr[t*FD + HF + d];
        }
    }
    #pragma unroll
    for(int t=0;t<NT;t++){
        float a0=warpsum(acc[t][0]), a1=warpsum(acc[t][1]);
        if(lane==0){ g_s1[warp*NT+t]=a0; g_s2[warp*NT+t]=a1; }
    }
}

// ---------------- k4: per-batch stable-pack positions via prefix scan ----------------
__global__ void k4_scan(){
    int b = blockIdx.x;
    __shared__ unsigned char selS[KK];
    __shared__ int wsum[32];
    __shared__ int totS;
    if(threadIdx.x < KK) selS[threadIdx.x] = (unsigned char)g_sel[b*KK + threadIdx.x];
    __syncthreads();
    const int CH = 5;                       // 1024*5 >= 5112
    int p0 = threadIdx.x*CH;
    unsigned char v[CH];
    int cnt = 0;
    #pragma unroll
    for(int c=0;c<CH;c++){
        int p = p0+c;
        int vv = 0;
        if(p < PP){
            int i = p/(KK-1), r = p%(KK-1);
            int j = (r<i) ? r : r+1;
            vv = selS[i] & selS[j];
        }
        v[c] = (unsigned char)vv; cnt += vv;
    }
    int lane = threadIdx.x&31, w = threadIdx.x>>5;
    int x = cnt;
    #pragma unroll
    for(int off=1;off<32;off<<=1){ int y=__shfl_up_sync(0xffffffffu,x,off); if(lane>=off) x+=y; }
    if(lane==31) wsum[w]=x;
    __syncthreads();
    if(w==0){
        int y = wsum[lane];
        #pragma unroll
        for(int off=1;off<32;off<<=1){ int z=__shfl_up_sync(0xffffffffu,y,off); if(lane>=off) y+=z; }
        wsum[lane]=y;
        if(lane==31) totS=y;
    }
    __syncthreads();
    int excl  = x - cnt + (w>0 ? wsum[w-1] : 0);
    int total = totS;
    int vb = excl;
    #pragma unroll
    for(int c=0;c<CH;c++){
        int p = p0+c;
        if(p < PP){
            g_pos[b*PP+p] = v[c] ? vb : total + (p - vb);
            vb += v[c];
        }
    }
}

// ---------------- k5: emit pair_logits / tr_targets + class segment max ----------------
__global__ void k5_pairs(const float* __restrict__ TR, const float* __restrict__ b_tr,
                         const int* __restrict__ lookup, float* __restrict__ out){
    int idx = blockIdx.x*blockDim.x + threadIdx.x;
    if(idx >= BN*PP) return;
    int b = idx/PP, p = idx%PP;
    int i = p/(KK-1), r = p%(KK-1);
    int j = (r<i) ? r : r+1;
    int q = g_pos[idx];
    float* pl = out + OFF_PL + ((size_t)b*PP + q)*NT;
    float* tt = out + OFF_TT + ((size_t)b*PP + q)*NT;
    bool valid = g_sel[b*KK+i] && g_sel[b*KK+j];
    if(valid){
        int aai = g_aaidx[b*KK+i], aaj = g_aaidx[b*KK+j];
        const int* lk = lookup + ((size_t)aai*NAA + aaj)*NT;
        #pragma unroll
        for(int t=0;t<NT;t++){
            float l = g_s1[(b*KK+i)*NT+t] + g_s2[(b*KK+j)*NT+t] + b_tr[t];
            pl[t] = l;
            tt[t] = TR[(((size_t)b*KK + i)*KK + j)*NT + t];
            int c = lk[t];
            atomicMax(&g_segmax[b*NC + c], fmap(l));
            atomicAdd(&g_count[b*NC + c], 1);
        }
    } else {
        #pragma unroll
        for(int t=0;t<NT;t++){ pl[t]=g_invconst[t]; tt[t]=-1.0f; }
    }
}

// ---------------- k6: finalize class outputs ----------------
__global__ void k6_final(float* __restrict__ out){
    int idx = blockIdx.x*blockDim.x + threadIdx.x;
    if(idx >= BN*NC) return;
    out[OFF_FINAL + idx] = (g_count[idx] > 0) ? funmap(g_segmax[idx]) : g_nonexist[idx];
}

extern "C" void kernel_launch(void* const* d_in, const int* in_sizes, int n_in,
                              void* d_out, int out_size){
    const float* inp     = (const float*)d_in[0];
    const float* objmask = (const float*)d_in[1];
    const float* TR      = (const float*)d_in[2];
    const float* W_obj   = (const float*)d_in[3];
    const float* b_obj   = (const float*)d_in[4];
    const float* W_act   = (const float*)d_in[5];
    const float* b_act   = (const float*)d_in[6];
    const float* W_tr    = (const float*)d_in[7];
    const float* b_tr    = (const float*)d_in[8];
    const float* W_ne    = (const float*)d_in[9];
    const float* b_ne    = (const float*)d_in[10];
    const float* obj_emb = (const float*)d_in[11];
    const float* act_emb = (const float*)d_in[12];
    const int*   AA      = (const int*)d_in[13];
    // d_in[14] = obj_act_lookup (eval-branch only, unused)
    const int*   lookup  = (const int*)d_in[15];
    float* out = (float*)d_out;

    k0_init<<<(BN*NC+255)/256, 256>>>();
    k1_heads<<<BN*MO, 256>>>(inp, objmask, W_obj, b_obj, W_act, b_act, AA, out);
    k2_pool<<<BN, 256>>>(inp, objmask, W_ne, b_ne, W_tr, b_tr);
    k3_slots<<<(BN*KK*32 + 255)/256, 256>>>(inp, obj_emb, act_emb, W_tr);
    k4_scan<<<BN, 1024>>>();
    k5_pairs<<<(BN*PP + 255)/256, 256>>>(TR, b_tr, lookup, out);
    k6_final<<<(BN*NC + 255)/256, 256>>>(out);
}

// round 2
// speedup vs baseline: 2.3285x; 2.3285x over previous
#include <cuda_runtime.h>
#include <cuda_bf16.h>

#define BN 8
#define MO 12
#define DD 512
#define NO 37
#define NA 6
#define NT 3
#define EM 128
#define NAA 100
#define NC 300
#define KK 72
#define PP 5112            // KK*(KK-1)
#define FD 1536
#define HF 768
#define CHUNKS 20          // ceil(PP/256)

// output layout (flattened, tuple order)
#define OFF_FINAL 0
#define OFF_PL    (BN*NC)
#define OFF_TT    (OFF_PL + BN*PP*NT)
#define OFF_ACT   (OFF_TT + BN*PP*NT)
#define OFF_OBJ   (OFF_ACT + BN*MO*NA)

// ---------------- device scratch ----------------
__device__ float    g_s1[BN*KK*NT];
__device__ float    g_s2[BN*KK*NT];
__device__ int      g_pos[BN*PP];
__device__ int      g_sel[BN*KK];
__device__ int      g_aaidx[BN*KK];
__device__ int      g_objidx[BN*MO];
__device__ float    g_inpdot[BN*MO*6];     // [bo][t][h]
__device__ float    g_objtab[NO*6];        // [oi][t][h]
__device__ float    g_acttab[NA*6];        // [a][t][h]
__device__ float    g_nonexist[BN*NC];
__device__ unsigned g_segmax[BN*NC];
__device__ float    g_invconst[NT];

__device__ __forceinline__ float warpsum(float v){
    #pragma unroll
    for(int o=16;o>0;o>>=1) v += __shfl_xor_sync(0xffffffffu, v, o);
    return v;
}
__device__ __forceinline__ unsigned fmap(float f){
    unsigned u=__float_as_uint(f);
    return (u & 0x80000000u) ? ~u : (u | 0x80000000u);
}
__device__ __forceinline__ float funmap(unsigned u){
    return __uint_as_float((u & 0x80000000u) ? (u ^ 0x80000000u) : ~u);
}
__device__ __forceinline__ float dot4(float4 a, float4 b){
    return a.x*b.x + a.y*b.y + a.z*b.z + a.w*b.w;
}

// ================ kA: heads + pool + tables + clear (all independent) ================
// blocks [0,96): per-(b,obj) heads + inp half-dots
// blocks [96,112): pool/non_exist (2 blocks per batch)
// block  112: obj/act emb tables + invconst
// block  113: clear segmax
__global__ void kA(const float* __restrict__ inp, const float* __restrict__ objmask,
                   const float* __restrict__ W_obj, const float* __restrict__ b_obj,
                   const float* __restrict__ W_act, const float* __restrict__ b_act,
                   const float* __restrict__ W_tr,  const float* __restrict__ b_tr,
                   const float* __restrict__ W_ne,  const float* __restrict__ b_ne,
                   const float* __restrict__ obj_emb, const float* __restrict__ act_emb,
                   const int* __restrict__ AA, float* __restrict__ out){
    int blk = blockIdx.x;
    int tid = threadIdx.x, w = tid>>5, lane = tid&31;

    if(blk < BN*MO){
        // ---- heads: 37 obj + 6 act + 6 W_tr-half dots, all over the same 512-row ----
        __shared__ float4 row[DD/4];
        __shared__ float  res[NO+NA];
        int bo = blk, b = bo/MO, o = bo%MO;
        const float4* ir = (const float4*)(inp + (size_t)bo*DD);
        for(int d=tid; d<DD/4; d+=blockDim.x) row[d]=ir[d];
        __syncthreads();
        for(int c=w; c<NO+NA+6; c+=8){
            const float4* W;
            if(c<NO)            W = (const float4*)(W_obj + (size_t)c*DD);
            else if(c<NO+NA)    W = (const float4*)(W_act + (size_t)(c-NO)*DD);
            else { int idx=c-NO-NA; int t=idx>>1, h=idx&1;
                   W = (const float4*)(W_tr + (size_t)t*FD + h*HF); }
            float acc=0.f;
            #pragma unroll
            for(int d=lane; d<DD/4; d+=32) acc += dot4(row[d], W[d]);
            acc = warpsum(acc);
            if(lane==0){
                if(c<NO){ float v=acc+b_obj[c]; res[c]=v; out[OFF_OBJ + bo*NO + c]=v; }
                else if(c<NO+NA){ float v=acc+b_act[c-NO]; res[c]=v; out[OFF_ACT + bo*NA + (c-NO)]=v; }
                else g_inpdot[bo*6 + (c-NO-NA)] = acc;
            }
        }
        __syncthreads();
        if(tid==0){
            int best=0; float bv=res[0];
            #pragma unroll
            for(int c=1;c<NO;c++) if(res[c]>bv){ bv=res[c]; best=c; }
            g_objidx[bo]=best;
        }
        if(tid < NA){
            int a=tid, k=o*NA+a;
            bool act_on = (res[NO+a] > 0.0f) && (objmask[bo] == 1.0f);
            int  aa = AA[b*KK + k];
            bool s  = act_on && (aa != -1);
            g_sel[b*KK+k]   = s ? 1 : 0;
            g_aaidx[b*KK+k] = s ? aa : -1;
        }
    } else if(blk < BN*MO + BN*2){
        // ---- pool -> non_exist_out (2 blocks/batch, 150 classes each) ----
        int bb = blk - BN*MO;
        int b = bb>>1, half = bb&1;
        __shared__ float4 pooled[DD/4];
        __shared__ float  msum_s;
        if(tid==0){
            float m=0.f;
            for(int o=0;o<MO;o++) m += objmask[b*MO+o];
            msum_s=m;
        }
        __syncthreads();
        float inv = 1.0f/msum_s;
        for(int d4=tid; d4<DD/4; d4+=blockDim.x){
            float4 s = make_float4(0,0,0,0);
            for(int o=0;o<MO;o++){
                float m = objmask[b*MO+o];
                float4 v = ((const float4*)(inp + ((size_t)b*MO+o)*DD))[d4];
                s.x += v.x*m; s.y += v.y*m; s.z += v.z*m; s.w += v.w*m;
            }
            pooled[d4] = make_float4(s.x*inv, s.y*inv, s.z*inv, s.w*inv);
        }
        __syncthreads();
        int c0 = half*150, c1 = c0+150;
        for(int c=c0+w; c<c1; c+=8){
            const float4* W = (const float4*)(W_ne + (size_t)c*DD);
            float acc=0.f;
            #pragma unroll
            for(int d=lane; d<DD/4; d+=32) acc += dot4(pooled[d], W[d]);
            acc = warpsum(acc);
            if(lane==0) g_nonexist[b*NC+c] = acc + b_ne[c];
        }
    } else if(blk == BN*MO + BN*2){
        // ---- emb tables: objtab[37][6], acttab[6][6] (dims=128); invconst[3] (dims=1536) ----
        for(int c=w; c<NO*6 + NA*6; c+=8){
            const float* src; const float* Wv;
            if(c < NO*6){
                int oi=c/6, idx=c%6, t=idx>>1, h=idx&1;
                src = obj_emb + (size_t)oi*EM;
                Wv  = W_tr + (size_t)t*FD + h*HF + DD;
            } else {
                int cc=c-NO*6; int a=cc/6, idx=cc%6, t=idx>>1, h=idx&1;
                src = act_emb + (size_t)a*EM;
                Wv  = W_tr + (size_t)t*FD + h*HF + DD + EM;
            }
            float4 a4 = ((const float4*)src)[lane];
            float4 b4 = ((const float4*)Wv)[lane];
            float acc = warpsum(dot4(a4,b4));
            if(lane==0){
                if(c < NO*6) g_objtab[c] = acc;
                else         g_acttab[c-NO*6] = acc;
            }
        }
        if(w < NT){
            const float4* W = (const float4*)(W_tr + (size_t)w*FD);
            float acc=0.f;
            #pragma unroll
            for(int d=lane; d<FD/4; d+=32) acc += W[d].x+W[d].y+W[d].z+W[d].w;
            acc = warpsum(acc);
            if(lane==0) g_invconst[w] = b_tr[w] - acc;
        }
    } else {
        for(int i=tid; i<BN*NC; i+=blockDim.x) g_segmax[i]=0u;
    }
}

// ================ kB: slot combine + stable-pack scan ================
__global__ void kB(){
    int b = blockIdx.x, tid = threadIdx.x;
    if(tid < KK){
        int k=tid, o=k/NA, a=k%NA;
        int oi = g_objidx[b*MO+o];
        #pragma unroll
        for(int t=0;t<NT;t++){
            g_s1[(b*KK+k)*NT+t] = g_inpdot[(b*MO+o)*6 + t*2+0] + g_objtab[oi*6 + t*2+0] + g_acttab[a*6 + t*2+0];
            g_s2[(b*KK+k)*NT+t] = g_inpdot[(b*MO+o)*6 + t*2+1] + g_objtab[oi*6 + t*2+1] + g_acttab[a*6 + t*2+1];
        }
    }
    __shared__ unsigned char selS[KK];
    __shared__ int wsum[32];
    __shared__ int totS;
    if(tid < KK) selS[tid] = (unsigned char)g_sel[b*KK + tid];
    __syncthreads();
    const int CH = 5;                       // 1024*5 >= 5112
    int p0 = tid*CH;
    unsigned char v[CH];
    int cnt = 0;
    #pragma unroll
    for(int c=0;c<CH;c++){
        int p = p0+c;
        int vv = 0;
        if(p < PP){
            int i = p/(KK-1), r = p - i*(KK-1);
            int j = (r<i) ? r : r+1;
            vv = selS[i] & selS[j];
        }
        v[c] = (unsigned char)vv; cnt += vv;
    }
    int lane = tid&31, w = tid>>5;
    int x = cnt;
    #pragma unroll
    for(int off=1;off<32;off<<=1){ int y=__shfl_up_sync(0xffffffffu,x,off); if(lane>=off) x+=y; }
    if(lane==31) wsum[w]=x;
    __syncthreads();
    if(w==0){
        int y = wsum[lane];
        #pragma unroll
        for(int off=1;off<32;off<<=1){ int z=__shfl_up_sync(0xffffffffu,y,off); if(lane>=off) y+=z; }
        wsum[lane]=y;
        if(lane==31) totS=y;
    }
    __syncthreads();
    int excl  = x - cnt + (w>0 ? wsum[w-1] : 0);
    int total = totS;
    int vb = excl;
    #pragma unroll
    for(int c=0;c<CH;c++){
        int p = p0+c;
        if(p < PP){
            g_pos[b*PP+p] = v[c] ? vb : total + (p - vb);
            vb += v[c];
        }
    }
}

// ================ kC: pair logits / targets + class segment max ================
__global__ void kC(const float* __restrict__ TR, const float* __restrict__ b_tr,
                   const int* __restrict__ lookup, float* __restrict__ out){
    int b = blockIdx.x / CHUNKS, ch = blockIdx.x % CHUNKS;
    __shared__ float s1s[KK*NT], s2s[KK*NT], inv[NT], btr[NT];
    __shared__ int   aas[KK];
    __shared__ unsigned char sels[KK];
    int tid = threadIdx.x;
    for(int i=tid; i<KK*NT; i+=256){ s1s[i]=g_s1[b*KK*NT+i]; s2s[i]=g_s2[b*KK*NT+i]; }
    if(tid < KK){ aas[tid]=g_aaidx[b*KK+tid]; sels[tid]=(unsigned char)g_sel[b*KK+tid]; }
    if(tid < NT){ inv[tid]=g_invconst[tid]; btr[tid]=b_tr[tid]; }
    __syncthreads();
    int p = ch*256 + tid;
    if(p >= PP) return;
    int i = p/(KK-1), r = p - i*(KK-1);
    int j = (r<i) ? r : r+1;
    int q = g_pos[b*PP+p];
    float* pl = out + OFF_PL + ((size_t)b*PP + q)*NT;
    float* tt = out + OFF_TT + ((size_t)b*PP + q)*NT;
    if(sels[i] & sels[j]){
        const int*   lk  = lookup + ((size_t)aas[i]*NAA + aas[j])*NT;
        const float* trp = TR + (((size_t)b*KK + i)*KK + j)*NT;
        #pragma unroll
        for(int t=0;t<NT;t++){
            float l = s1s[i*NT+t] + s2s[j*NT+t] + btr[t];
            pl[t] = l;
            tt[t] = trp[t];
            atomicMax(&g_segmax[b*NC + lk[t]], fmap(l));
        }
    } else {
        #pragma unroll
        for(int t=0;t<NT;t++){ pl[t]=inv[t]; tt[t]=-1.0f; }
    }
}

// ================ kD: finalize ================
__global__ void kD(float* __restrict__ out){
    int idx = blockIdx.x*blockDim.x + threadIdx.x;
    if(idx >= BN*NC) return;
    unsigned u = g_segmax[idx];
    out[OFF_FINAL + idx] = u ? funmap(u) : g_nonexist[idx];
}

extern "C" void kernel_launch(void* const* d_in, const int* in_sizes, int n_in,
                              void* d_out, int out_size){
    const float* inp     = (const float*)d_in[0];
    const float* objmask = (const float*)d_in[1];
    const float* TR      = (const float*)d_in[2];
    const float* W_obj   = (const float*)d_in[3];
    const float* b_obj   = (const float*)d_in[4];
    const float* W_act   = (const float*)d_in[5];
    const float* b_act   = (const float*)d_in[6];
    const float* W_tr    = (const float*)d_in[7];
    const float* b_tr    = (const float*)d_in[8];
    const float* W_ne    = (const float*)d_in[9];
    const float* b_ne    = (const float*)d_in[10];
    const float* obj_emb = (const float*)d_in[11];
    const float* act_emb = (const float*)d_in[12];
    const int*   AA      = (const int*)d_in[13];
    const int*   lookup  = (const int*)d_in[15];
    float* out = (float*)d_out;

    kA<<<BN*MO + BN*2 + 2, 256>>>(inp, objmask, W_obj, b_obj, W_act, b_act,
                                  W_tr, b_tr, W_ne, b_ne, obj_emb, act_emb, AA, out);
    kB<<<BN, 1024>>>();
    kC<<<BN*CHUNKS, 256>>>(TR, b_tr, lookup, out);
    kD<<<(BN*NC + 255)/256, 256>>>(out);
}

// round 3
// speedup vs baseline: 3.3163x; 1.4242x over previous
#include <cuda_runtime.h>
#include <cuda_bf16.h>

#define BN 8
#define MO 12
#define DD 512
#define NO 37
#define NA 6
#define NT 3
#define EM 128
#define NAA 100
#define NC 300
#define KK 72
#define PP 5112            // KK*(KK-1)
#define FD 1536
#define HF 768
#define CHUNKS 20          // ceil(PP/256)
#define NCB (BN*CHUNKS)    // kC grid size = 160

// kA grid layout
#define HEADB (BN*MO)      // 96 head blocks
#define PPB   8            // pool parts per batch
#define POOLB (BN*PPB)     // 64 pool blocks
#define TABB  4            // table blocks
#define KA_GRID (HEADB + POOLB + TABB + 1)

// output layout (flattened, tuple order)
#define OFF_FINAL 0
#define OFF_PL    (BN*NC)
#define OFF_TT    (OFF_PL + BN*PP*NT)
#define OFF_ACT   (OFF_TT + BN*PP*NT)
#define OFF_OBJ   (OFF_ACT + BN*MO*NA)

// ---------------- device scratch ----------------
__device__ int      g_sel6[BN*MO];         // 6-bit selection mask per (b,obj)
__device__ int      g_aaidx[BN*KK];
__device__ int      g_objidx[BN*MO];
__device__ float    g_inpdot[BN*MO*6];     // [bo][t*2+h]
__device__ float    g_objtab[NO*6];        // [oi][t*2+h]
__device__ float    g_acttab[NA*6];        // [a][t*2+h]
__device__ float    g_nonexist[BN*NC];
__device__ unsigned g_segmax[BN*NC];
__device__ float    g_invconst[NT];
__device__ int      g_ctr;

__device__ __forceinline__ float warpsum(float v){
    #pragma unroll
    for(int o=16;o>0;o>>=1) v += __shfl_xor_sync(0xffffffffu, v, o);
    return v;
}
__device__ __forceinline__ unsigned fmap(float f){
    unsigned u=__float_as_uint(f);
    return (u & 0x80000000u) ? ~u : (u | 0x80000000u);
}
__device__ __forceinline__ float funmap(unsigned u){
    return __uint_as_float((u & 0x80000000u) ? (u ^ 0x80000000u) : ~u);
}
__device__ __forceinline__ float dot4(float4 a, float4 b){
    return a.x*b.x + a.y*b.y + a.z*b.z + a.w*b.w;
}

// ================ kA: heads + pool + tables + clear (all independent) ================
__global__ __launch_bounds__(512) void
kA(const float* __restrict__ inp, const float* __restrict__ objmask,
   const float* __restrict__ W_obj, const float* __restrict__ b_obj,
   const float* __restrict__ W_act, const float* __restrict__ b_act,
   const float* __restrict__ W_tr,  const float* __restrict__ b_tr,
   const float* __restrict__ W_ne,  const float* __restrict__ b_ne,
   const float* __restrict__ obj_emb, const float* __restrict__ act_emb,
   const int* __restrict__ AA, float* __restrict__ out){
    int blk = blockIdx.x;
    int tid = threadIdx.x, w = tid>>5, lane = tid&31;

    if(blk < HEADB){
        // ---- heads: 37 obj + 6 act + 6 W_tr-half dots over one 512-dim row ----
        __shared__ float4 row[DD/4];
        __shared__ float  res[NO+NA];
        int bo = blk, b = bo/MO, o = bo%MO;
        const float4* ir = (const float4*)(inp + (size_t)bo*DD);
        if(tid < DD/4) row[tid]=ir[tid];
        __syncthreads();
        for(int c=w; c<NO+NA+6; c+=16){
            const float4* W;
            if(c<NO)            W = (const float4*)(W_obj + (size_t)c*DD);
            else if(c<NO+NA)    W = (const float4*)(W_act + (size_t)(c-NO)*DD);
            else { int idx=c-NO-NA; int t=idx>>1, h=idx&1;
                   W = (const float4*)(W_tr + (size_t)t*FD + h*HF); }
            float acc=0.f;
            #pragma unroll
            for(int d=lane; d<DD/4; d+=32) acc += dot4(row[d], W[d]);
            acc = warpsum(acc);
            if(lane==0){
                if(c<NO){ float v=acc+b_obj[c]; res[c]=v; out[OFF_OBJ + bo*NO + c]=v; }
                else if(c<NO+NA){ float v=acc+b_act[c-NO]; res[c]=v; out[OFF_ACT + bo*NA + (c-NO)]=v; }
                else g_inpdot[bo*6 + (c-NO-NA)] = acc;
            }
        }
        __syncthreads();
        if(tid==0){
            int best=0; float bv=res[0];
            #pragma unroll
            for(int c=1;c<NO;c++) if(res[c]>bv){ bv=res[c]; best=c; }
            g_objidx[bo]=best;
        }
        if(w==0){
            bool s=false;
            if(lane < NA){
                int k = o*NA + lane;
                bool act_on = (res[NO+lane] > 0.0f) && (objmask[bo] == 1.0f);
                int  aa = AA[b*KK + k];
                s = act_on && (aa != -1);
                g_aaidx[b*KK+k] = s ? aa : -1;
            }
            unsigned m = __ballot_sync(0xffffffffu, s);
            if(lane==0) g_sel6[bo] = (int)(m & 0x3fu);
        }
    } else if(blk < HEADB + POOLB){
        // ---- pool -> non_exist_out (8 parts per batch) ----
        int bb = blk - HEADB;
        int b = bb/PPB, part = bb%PPB;
        __shared__ float4 pooled[DD/4];
        __shared__ float  msum_s;
        if(tid==0){
            float m=0.f;
            for(int o=0;o<MO;o++) m += objmask[b*MO+o];
            msum_s=m;
        }
        __syncthreads();
        float inv = 1.0f/msum_s;
        if(tid < DD/4){
            float4 s = make_float4(0,0,0,0);
            #pragma unroll
            for(int o=0;o<MO;o++){
                float m = objmask[b*MO+o];
                float4 v = ((const float4*)(inp + ((size_t)b*MO+o)*DD))[tid];
                s.x += v.x*m; s.y += v.y*m; s.z += v.z*m; s.w += v.w*m;
            }
            pooled[tid] = make_float4(s.x*inv, s.y*inv, s.z*inv, s.w*inv);
        }
        __syncthreads();
        int c0 = part*38, c1 = c0+38; if(c1>NC) c1=NC;
        for(int c=c0+w; c<c1; c+=16){
            const float4* W = (const float4*)(W_ne + (size_t)c*DD);
            float acc=0.f;
            #pragma unroll
            for(int d=lane; d<DD/4; d+=32) acc += dot4(pooled[d], W[d]);
            acc = warpsum(acc);
            if(lane==0) g_nonexist[b*NC+c] = acc + b_ne[c];
        }
    } else if(blk < HEADB + POOLB + TABB){
        // ---- emb tables (258 dot-128s) + invconst (3 dot-1536s) across 4 blocks ----
        int gw = (blk - HEADB - POOLB)*16 + w;      // 0..63
        for(int c=gw; c<NO*6 + NA*6 + NT; c+=64){
            if(c < NO*6 + NA*6){
                const float* src; const float* Wv;
                if(c < NO*6){
                    int oi=c/6, idx=c%6, t=idx>>1, h=idx&1;
                    src = obj_emb + (size_t)oi*EM;
                    Wv  = W_tr + (size_t)t*FD + h*HF + DD;
                } else {
                    int cc=c-NO*6; int a=cc/6, idx=cc%6, t=idx>>1, h=idx&1;
                    src = act_emb + (size_t)a*EM;
                    Wv  = W_tr + (size_t)t*FD + h*HF + DD + EM;
                }
                float4 a4 = ((const float4*)src)[lane];
                float4 b4 = ((const float4*)Wv)[lane];
                float acc = warpsum(dot4(a4,b4));
                if(lane==0){
                    if(c < NO*6) g_objtab[c] = acc;
                    else         g_acttab[c-NO*6] = acc;
                }
            } else {
                int t = c - NO*6 - NA*6;
                const float4* W = (const float4*)(W_tr + (size_t)t*FD);
                float acc=0.f;
                #pragma unroll
                for(int d=lane; d<FD/4; d+=32) acc += W[d].x+W[d].y+W[d].z+W[d].w;
                acc = warpsum(acc);
                if(lane==0) g_invconst[t] = b_tr[t] - acc;
            }
        }
    } else {
        for(int i=tid; i<BN*NC; i+=512) g_segmax[i]=0u;
        if(tid==0) g_ctr=0;
    }
}

// ================ kC: pair logits/targets + segment max + tail finalize ================
__global__ __launch_bounds__(256) void
kC(const float* __restrict__ TR, const float* __restrict__ b_tr,
   const int* __restrict__ lookup, float* __restrict__ out){
    int b = blockIdx.x / CHUNKS, ch = blockIdx.x % CHUNKS;
    __shared__ float s1s[KK*NT], s2s[KK*NT], inv[NT], btr[NT];
    __shared__ int   aas[KK], sel6s[MO];
    __shared__ short cps[KK+1];
    __shared__ unsigned char sels[KK];
    __shared__ int   lastF;
    int tid = threadIdx.x;

    if(tid < MO) sel6s[tid] = g_sel6[b*MO+tid];
    if(tid < KK){
        int k=tid, o=k/NA, a=k%NA;
        int oi = g_objidx[b*MO+o];
        aas[k] = g_aaidx[b*KK+k];
        #pragma unroll
        for(int t=0;t<NT;t++){
            s1s[k*NT+t] = g_inpdot[(b*MO+o)*6 + t*2+0] + g_objtab[oi*6 + t*2+0] + g_acttab[a*6 + t*2+0];
            s2s[k*NT+t] = g_inpdot[(b*MO+o)*6 + t*2+1] + g_objtab[oi*6 + t*2+1] + g_acttab[a*6 + t*2+1];
        }
    }
    if(tid < NT){ inv[tid]=g_invconst[tid]; btr[tid]=b_tr[tid]; }
    __syncthreads();
    if(tid <= KK){
        int full = tid/NA, rem = tid%NA, c = 0;
        for(int o=0;o<full;o++) c += __popc(sel6s[o]);
        if(tid < KK) c += __popc(sel6s[full] & ((1<<rem)-1));
        cps[tid] = (short)c;
        if(tid < KK) sels[tid] = (unsigned char)((sel6s[full]>>rem) & 1);
    }
    __syncthreads();

    int p = ch*256 + tid;
    if(p < PP){
        int S = cps[KK];
        int i = p/(KK-1), r = p - i*(KK-1);
        int j = (r<i) ? r : r+1;
        int si = sels[i];
        int vb = cps[i]*(S-1) + si*(cps[j] - (i<j ? 1 : 0));
        bool valid = si && sels[j];
        int q = valid ? vb : S*(S-1) + (p - vb);
        float* pl = out + OFF_PL + ((size_t)b*PP + q)*NT;
        float* tt = out + OFF_TT + ((size_t)b*PP + q)*NT;
        if(valid){
            const int*   lk  = lookup + ((size_t)aas[i]*NAA + aas[j])*NT;
            const float* trp = TR + (((size_t)b*KK + i)*KK + j)*NT;
            #pragma unroll
            for(int t=0;t<NT;t++){
                float l = s1s[i*NT+t] + s2s[j*NT+t] + btr[t];
                pl[t] = l;
                tt[t] = trp[t];
                atomicMax(&g_segmax[b*NC + lk[t]], fmap(l));
            }
        } else {
            #pragma unroll
            for(int t=0;t<NT;t++){ pl[t]=inv[t]; tt[t]=-1.0f; }
        }
    }

    // ---- last-block-done finalize ----
    __threadfence();
    __syncthreads();
    if(tid==0){
        int old = atomicAdd(&g_ctr, 1);
        lastF = (old == NCB-1);
    }
    __syncthreads();
    if(lastF){
        __threadfence();
        for(int idx=tid; idx<BN*NC; idx+=256){
            unsigned u = g_segmax[idx];
            out[OFF_FINAL + idx] = u ? funmap(u) : g_nonexist[idx];
        }
    }
}

extern "C" void kernel_launch(void* const* d_in, const int* in_sizes, int n_in,
                              void* d_out, int out_size){
    const float* inp     = (const float*)d_in[0];
    const float* objmask = (const float*)d_in[1];
    const float* TR      = (const float*)d_in[2];
    const float* W_obj   = (const float*)d_in[3];
    const float* b_obj   = (const float*)d_in[4];
    const float* W_act   = (const float*)d_in[5];
    const float* b_act   = (const float*)d_in[6];
    const float* W_tr    = (const float*)d_in[7];
    const float* b_tr    = (const float*)d_in[8];
    const float* W_ne    = (const float*)d_in[9];
    const float* b_ne    = (const float*)d_in[10];
    const float* obj_emb = (const float*)d_in[11];
    const float* act_emb = (const float*)d_in[12];
    const int*   AA      = (const int*)d_in[13];
    const int*   lookup  = (const int*)d_in[15];
    float* out = (float*)d_out;

    kA<<<KA_GRID, 512>>>(inp, objmask, W_obj, b_obj, W_act, b_act,
                         W_tr, b_tr, W_ne, b_ne, obj_emb, act_emb, AA, out);
    kC<<<NCB, 256>>>(TR, b_tr, lookup, out);
}

// round 4
// speedup vs baseline: 3.3226x; 1.0019x over previous
#include <cuda_runtime.h>
#include <cuda_bf16.h>

#define BN 8
#define MO 12
#define DD 512
#define NO 37
#define NA 6
#define NT 3
#define EM 128
#define NAA 100
#define NC 300
#define KK 72
#define PP 5112            // KK*(KK-1)
#define FD 1536
#define HF 768
#define TPB 512
#define PCH 10             // ceil(PP/512) pair-chunks per batch
#define PAIRB (BN*PCH)     // 80 pair blocks

// phase-1 grid layout
#define HEADB (BN*MO)              // 96
#define PPB   8
#define POOLB (BN*PPB)             // 64
#define TABB  4
#define GRID  (HEADB + POOLB + TABB + 1)   // 165

// output layout (flattened, tuple order)
#define OFF_FINAL 0
#define OFF_PL    (BN*NC)
#define OFF_TT    (OFF_PL + BN*PP*NT)
#define OFF_ACT   (OFF_TT + BN*PP*NT)
#define OFF_OBJ   (OFF_ACT + BN*MO*NA)

// ---------------- device scratch ----------------
__device__ int      g_sel6[BN*MO];
__device__ int      g_aaidx[BN*KK];
__device__ int      g_objidx[BN*MO];
__device__ float    g_inpdot[BN*MO*6];
__device__ float    g_objtab[NO*6];
__device__ float    g_acttab[NA*6];
__device__ float    g_nonexist[BN*NC];
__device__ unsigned g_segmax[BN*NC];
__device__ float    g_invconst[NT];
__device__ int      g_bar1;   // phase barrier (reset by tail block)
__device__ int      g_ctr2;   // completion counter (reset by tail block)

__device__ __forceinline__ float warpsum(float v){
    #pragma unroll
    for(int o=16;o>0;o>>=1) v += __shfl_xor_sync(0xffffffffu, v, o);
    return v;
}
__device__ __forceinline__ unsigned fmap(float f){
    unsigned u=__float_as_uint(f);
    return (u & 0x80000000u) ? ~u : (u | 0x80000000u);
}
__device__ __forceinline__ float funmap(unsigned u){
    return __uint_as_float((u & 0x80000000u) ? (u ^ 0x80000000u) : ~u);
}
__device__ __forceinline__ float dot4(float4 a, float4 b){
    return a.x*b.x + a.y*b.y + a.z*b.z + a.w*b.w;
}

// ================ single fused kernel ================
__global__ __launch_bounds__(TPB) void
kFused(const float* __restrict__ inp, const float* __restrict__ objmask,
       const float* __restrict__ W_obj, const float* __restrict__ b_obj,
       const float* __restrict__ W_act, const float* __restrict__ b_act,
       const float* __restrict__ W_tr,  const float* __restrict__ b_tr,
       const float* __restrict__ W_ne,  const float* __restrict__ b_ne,
       const float* __restrict__ obj_emb, const float* __restrict__ act_emb,
       const int* __restrict__ AA, const float* __restrict__ TR,
       const int* __restrict__ lookup, float* __restrict__ out){
    int blk = blockIdx.x;
    int tid = threadIdx.x, w = tid>>5, lane = tid&31;

    // ---------------- phase 1 ----------------
    if(blk < HEADB){
        __shared__ float4 row[DD/4];
        __shared__ float  res[NO+NA];
        int bo = blk, b = bo/MO, o = bo%MO;
        const float4* ir = (const float4*)(inp + (size_t)bo*DD);
        if(tid < DD/4) row[tid]=ir[tid];
        __syncthreads();
        for(int c=w; c<NO+NA+6; c+=16){
            const float4* W;
            if(c<NO)            W = (const float4*)(W_obj + (size_t)c*DD);
            else if(c<NO+NA)    W = (const float4*)(W_act + (size_t)(c-NO)*DD);
            else { int idx=c-NO-NA; int t=idx>>1, h=idx&1;
                   W = (const float4*)(W_tr + (size_t)t*FD + h*HF); }
            float acc=0.f;
            #pragma unroll
            for(int d=lane; d<DD/4; d+=32) acc += dot4(row[d], W[d]);
            acc = warpsum(acc);
            if(lane==0){
                if(c<NO){ float v=acc+b_obj[c]; res[c]=v; out[OFF_OBJ + bo*NO + c]=v; }
                else if(c<NO+NA){ float v=acc+b_act[c-NO]; res[c]=v; out[OFF_ACT + bo*NA + (c-NO)]=v; }
                else __stcg(&g_inpdot[bo*6 + (c-NO-NA)], acc);
            }
        }
        __syncthreads();
        if(tid==0){
            int best=0; float bv=res[0];
            #pragma unroll
            for(int c=1;c<NO;c++) if(res[c]>bv){ bv=res[c]; best=c; }
            __stcg(&g_objidx[bo], best);
        }
        if(w==0){
            bool s=false;
            if(lane < NA){
                int k = o*NA + lane;
                bool act_on = (res[NO+lane] > 0.0f) && (objmask[bo] == 1.0f);
                int  aa = AA[b*KK + k];
                s = act_on && (aa != -1);
                __stcg(&g_aaidx[b*KK+k], s ? aa : -1);
            }
            unsigned m = __ballot_sync(0xffffffffu, s);
            if(lane==0) __stcg(&g_sel6[bo], (int)(m & 0x3fu));
        }
    } else if(blk < HEADB + POOLB){
        int bb = blk - HEADB;
        int b = bb/PPB, part = bb%PPB;
        __shared__ float4 pooled[DD/4];
        __shared__ float  msum_s;
        if(tid==0){
            float m=0.f;
            for(int o=0;o<MO;o++) m += objmask[b*MO+o];
            msum_s=m;
        }
        __syncthreads();
        float inv = 1.0f/msum_s;
        if(tid < DD/4){
            float4 s = make_float4(0,0,0,0);
            #pragma unroll
            for(int o=0;o<MO;o++){
                float m = objmask[b*MO+o];
                float4 v = ((const float4*)(inp + ((size_t)b*MO+o)*DD))[tid];
                s.x += v.x*m; s.y += v.y*m; s.z += v.z*m; s.w += v.w*m;
            }
            pooled[tid] = make_float4(s.x*inv, s.y*inv, s.z*inv, s.w*inv);
        }
        __syncthreads();
        int c0 = part*38, c1 = c0+38; if(c1>NC) c1=NC;
        for(int c=c0+w; c<c1; c+=16){
            const float4* W = (const float4*)(W_ne + (size_t)c*DD);
            float acc=0.f;
            #pragma unroll
            for(int d=lane; d<DD/4; d+=32) acc += dot4(pooled[d], W[d]);
            acc = warpsum(acc);
            if(lane==0) __stcg(&g_nonexist[b*NC+c], acc + b_ne[c]);
        }
    } else if(blk < HEADB + POOLB + TABB){
        int gw = (blk - HEADB - POOLB)*16 + w;      // 0..63
        for(int c=gw; c<NO*6 + NA*6 + NT; c+=64){
            if(c < NO*6 + NA*6){
                const float* src; const float* Wv;
                if(c < NO*6){
                    int oi=c/6, idx=c%6, t=idx>>1, h=idx&1;
                    src = obj_emb + (size_t)oi*EM;
                    Wv  = W_tr + (size_t)t*FD + h*HF + DD;
                } else {
                    int cc=c-NO*6; int a=cc/6, idx=cc%6, t=idx>>1, h=idx&1;
                    src = act_emb + (size_t)a*EM;
                    Wv  = W_tr + (size_t)t*FD + h*HF + DD + EM;
                }
                float4 a4 = ((const float4*)src)[lane];
                float4 b4 = ((const float4*)Wv)[lane];
                float acc = warpsum(dot4(a4,b4));
                if(lane==0){
                    if(c < NO*6) __stcg(&g_objtab[c], acc);
                    else         __stcg(&g_acttab[c-NO*6], acc);
                }
            } else {
                int t = c - NO*6 - NA*6;
                const float4* W = (const float4*)(W_tr + (size_t)t*FD);
                float acc=0.f;
                #pragma unroll
                for(int d=lane; d<FD/4; d+=32) acc += W[d].x+W[d].y+W[d].z+W[d].w;
                acc = warpsum(acc);
                if(lane==0) __stcg(&g_invconst[t], b_tr[t] - acc);
            }
        }
    } else {
        for(int i=tid; i<BN*NC; i+=TPB) __stcg(&g_segmax[i], 0u);
    }

    // ---------------- device-wide barrier ----------------
    __threadfence();
    __syncthreads();
    if(tid==0){
        atomicAdd(&g_bar1, 1);
        while(*((volatile int*)&g_bar1) < GRID) { }
    }
    __syncthreads();
    __threadfence();

    // ---------------- phase 2: pairs ----------------
    if(blk < PAIRB){
        int b = blk / PCH, ch = blk % PCH;
        __shared__ float s1s[KK*NT], s2s[KK*NT], inv[NT], btr[NT];
        __shared__ int   aas[KK], sel6s[MO];
        __shared__ short cps[KK+1];
        __shared__ unsigned char sels[KK];

        if(tid < MO) sel6s[tid] = __ldcg(&g_sel6[b*MO+tid]);
        if(tid < KK){
            int k=tid, o=k/NA, a=k%NA;
            int oi = __ldcg(&g_objidx[b*MO+o]);
            aas[k] = __ldcg(&g_aaidx[b*KK+k]);
            #pragma unroll
            for(int t=0;t<NT;t++){
                s1s[k*NT+t] = __ldcg(&g_inpdot[(b*MO+o)*6 + t*2+0]) + __ldcg(&g_objtab[oi*6 + t*2+0]) + __ldcg(&g_acttab[a*6 + t*2+0]);
                s2s[k*NT+t] = __ldcg(&g_inpdot[(b*MO+o)*6 + t*2+1]) + __ldcg(&g_objtab[oi*6 + t*2+1]) + __ldcg(&g_acttab[a*6 + t*2+1]);
            }
        }
        if(tid < NT){ inv[tid]=__ldcg(&g_invconst[tid]); btr[tid]=b_tr[tid]; }
        __syncthreads();
        if(tid <= KK){
            int full = tid/NA, rem = tid%NA, c = 0;
            for(int o=0;o<full;o++) c += __popc(sel6s[o]);
            if(tid < KK) c += __popc(sel6s[full] & ((1<<rem)-1));
            cps[tid] = (short)c;
            if(tid < KK) sels[tid] = (unsigned char)((sel6s[full]>>rem) & 1);
        }
        __syncthreads();

        int p = ch*TPB + tid;
        if(p < PP){
            int S = cps[KK];
            int i = p/(KK-1), r = p - i*(KK-1);
            int j = (r<i) ? r : r+1;
            int si = sels[i];
            int vb = cps[i]*(S-1) + si*(cps[j] - (i<j ? 1 : 0));
            bool valid = si && sels[j];
            int q = valid ? vb : S*(S-1) + (p - vb);
            float* pl = out + OFF_PL + ((size_t)b*PP + q)*NT;
            float* tt = out + OFF_TT + ((size_t)b*PP + q)*NT;
            if(valid){
                const int*   lk  = lookup + ((size_t)aas[i]*NAA + aas[j])*NT;
                const float* trp = TR + (((size_t)b*KK + i)*KK + j)*NT;
                #pragma unroll
                for(int t=0;t<NT;t++){
                    float l = s1s[i*NT+t] + s2s[j*NT+t] + btr[t];
                    pl[t] = l;
                    tt[t] = trp[t];
                    atomicMax(&g_segmax[b*NC + lk[t]], fmap(l));
                }
            } else {
                #pragma unroll
                for(int t=0;t<NT;t++){ pl[t]=inv[t]; tt[t]=-1.0f; }
            }
        }
    }

    // ---------------- tail finalize ----------------
    __shared__ int lastF;
    __threadfence();
    __syncthreads();
    if(tid==0){
        int old = atomicAdd(&g_ctr2, 1);
        lastF = (old == GRID-1);
    }
    __syncthreads();
    if(lastF){
        __threadfence();
        for(int idx=tid; idx<BN*NC; idx+=TPB){
            unsigned u = __ldcg(&g_segmax[idx]);
            out[OFF_FINAL + idx] = u ? funmap(u) : __ldcg(&g_nonexist[idx]);
        }
        // reset counters for next graph replay (all blocks have passed both sync points)
        if(tid==0){
            *((volatile int*)&g_bar1) = 0;
            *((volatile int*)&g_ctr2) = 0;
        }
    }
}

extern "C" void kernel_launch(void* const* d_in, const int* in_sizes, int n_in,
                              void* d_out, int out_size){
    const float* inp     = (const float*)d_in[0];
    const float* objmask = (const float*)d_in[1];
    const float* TR      = (const float*)d_in[2];
    const float* W_obj   = (const float*)d_in[3];
    const float* b_obj   = (const float*)d_in[4];
    const float* W_act   = (const float*)d_in[5];
    const float* b_act   = (const float*)d_in[6];
    const float* W_tr    = (const float*)d_in[7];
    const float* b_tr    = (const float*)d_in[8];
    const float* W_ne    = (const float*)d_in[9];
    const float* b_ne    = (const float*)d_in[10];
    const float* obj_emb = (const float*)d_in[11];
    const float* act_emb = (const float*)d_in[12];
    const int*   AA      = (const int*)d_in[13];
    const int*   lookup  = (const int*)d_in[15];
    float* out = (float*)d_out;

    kFused<<<GRID, TPB>>>(inp, objmask, W_obj, b_obj, W_act, b_act,
                          W_tr, b_tr, W_ne, b_ne, obj_emb, act_emb,
                          AA, TR, lookup, out);
}